// round 16
// baseline (speedup 1.0000x reference)
#include <cuda_runtime.h>
#include <cuda_fp16.h>

#define T_DIM 200
#define B_DIM 64
#define E_DIM 64
#define NROWS (T_DIM * B_DIM)   // 12800
#define BH (B_DIM * E_DIM)      // 4096
#define LOG2E 1.4426950408889634f

// ---- scratch ----
__device__ __half2 g_x1h[NROWS * 32];   // x1 pre-scaled by 0.5, half2 packed
__device__ float   g_y2[NROWS * E_DIM];
__device__ float   g_y3[NROWS * E_DIM];
__device__ __half  g_qh[NROWS * E_DIM]; // q pre-scaled by 0.5, half
__device__ float   g_ma[NROWS * E_DIM];
__device__ float   g_t1[4 * NROWS * 32];  // tower L1 outputs

__constant__ int c_IBB[16] = {0,1,2,2,3,3,4,4,4,5,5,5,6,6,6,6};
__constant__ int c_JC [16] = {0,0,0,1,0,1,0,1,2,0,1,2,0,1,2,3};

__device__ __forceinline__ float ex2f(float x) {
    float r; asm("ex2.approx.f32 %0, %1;" : "=f"(r) : "f"(x)); return r;
}
__device__ __forceinline__ float rcpf(float x) {
    float r; asm("rcp.approx.f32 %0, %1;" : "=f"(r) : "f"(x)); return r;
}
__device__ __forceinline__ float sigf(float v) {
    return rcpf(1.0f + ex2f(-v * LOG2E));
}
__device__ __forceinline__ float leakyf(float v) {
    return (v >= 0.0f) ? v : 0.3f * v;
}
// ---- f16x2 helpers ----
__device__ __forceinline__ unsigned tanh2u(unsigned x) {
    unsigned r; asm("tanh.approx.f16x2 %0, %1;" : "=r"(r) : "r"(x)); return r;
}
__device__ __forceinline__ unsigned hadd2u(unsigned a, unsigned b) {
    unsigned r; asm("add.f16x2 %0, %1, %2;" : "=r"(r) : "r"(a), "r"(b)); return r;
}
__device__ __forceinline__ unsigned hfma2u(unsigned a, unsigned b, unsigned c) {
    unsigned r; asm("fma.rn.f16x2 %0, %1, %2, %3;" : "=r"(r) : "r"(a), "r"(b), "r"(c)); return r;
}
__device__ __forceinline__ unsigned f2h2(float hi, float lo) {
    unsigned r; asm("cvt.rn.f16x2.f32 %0, %1, %2;" : "=r"(r) : "f"(hi), "f"(lo)); return r;
}
__device__ __forceinline__ float2 h22f2(unsigned u) {
    float2 f;
    asm("{ .reg .f16 l, h; mov.b32 {l, h}, %2; cvt.f32.f16 %0, l; cvt.f32.f16 %1, h; }"
        : "=f"(f.x), "=f"(f.y) : "r"(u));
    return f;
}
// ---- f32x2 helpers ----
__device__ __forceinline__ unsigned long long pk2(float v) {
    unsigned long long r; asm("mov.b64 %0, {%1, %1};" : "=l"(r) : "f"(v)); return r;
}
__device__ __forceinline__ void ffma2(unsigned long long& d,
                                      unsigned long long a, unsigned long long b) {
    asm("fma.rn.f32x2 %0, %1, %2, %0;" : "+l"(d) : "l"(a), "l"(b));
}
__device__ __forceinline__ float2 up2(unsigned long long v) {
    float2 f; asm("mov.b64 {%0, %1}, %2;" : "=f"(f.x), "=f"(f.y) : "l"(v)); return f;
}
// ---- tf32 mma (m16n8k8, row.col) ----
__device__ __forceinline__ void mma_tf32(float& d0, float& d1, float& d2, float& d3,
                                         unsigned a0, unsigned a1, unsigned a2, unsigned a3,
                                         unsigned b0, unsigned b1) {
    asm volatile(
        "mma.sync.aligned.m16n8k8.row.col.f32.tf32.tf32.f32 "
        "{%0,%1,%2,%3},{%4,%5,%6,%7},{%8,%9},{%0,%1,%2,%3};"
        : "+f"(d0), "+f"(d1), "+f"(d2), "+f"(d3)
        : "r"(a0), "r"(a1), "r"(a2), "r"(a3), "r"(b0), "r"(b1));
}
#define FU(x) __float_as_uint(x)

// ============================================================================
// GEMM (HOUT=64), up to 3 towers, f32x2 inner, 64-row tiles. (unchanged)
// ============================================================================
struct GemmBatch {
    const float* X[3];
    const float* W[3];
    const float* B[3];
    float*       Y[3];
    int          act[3];
};

__global__ void __launch_bounds__(256) gemm64_k(GemmBatch gb)
{
    constexpr int ROWS = 64;
    __shared__ __align__(16) float Xt[64][ROWS + 4];
    __shared__ __align__(16) float Ws[64][64];
    __shared__ float Bs[64];

    const int tw = blockIdx.y;
    const float* __restrict__ X  = gb.X[tw];
    const float* __restrict__ W  = gb.W[tw];
    const float* __restrict__ Bp = gb.B[tw];
    float* __restrict__ Y        = gb.Y[tw];
    const int act = gb.act[tw];

    const int tid = threadIdx.x;
    const int r0  = blockIdx.x * ROWS;

    for (int idx = tid; idx < 1024; idx += 256)
        *(((float4*)Ws) + idx) = ((const float4*)W)[idx];
    if (tid < 64) Bs[tid] = Bp ? Bp[tid] : 0.0f;
    for (int idx = tid; idx < ROWS * 16; idx += 256) {
        int r  = idx & 63;
        int k4 = (idx >> 6) << 2;
        float4 v = *(const float4*)&X[(size_t)(r0 + r) * 64 + k4];
        Xt[k4 + 0][r] = v.x; Xt[k4 + 1][r] = v.y;
        Xt[k4 + 2][r] = v.z; Xt[k4 + 3][r] = v.w;
    }
    __syncthreads();

    const int tc = tid & 15;
    const int tr = tid >> 4;
    unsigned long long acc[2][4];
    #pragma unroll
    for (int p = 0; p < 2; p++)
        #pragma unroll
        for (int c = 0; c < 4; c++) acc[p][c] = 0ull;

    #pragma unroll 8
    for (int k = 0; k < 64; k++) {
        ulonglong2 X0 = *(const ulonglong2*)&Xt[k][tr * 4];
        float4 wv = *(const float4*)&Ws[k][tc * 4];
        unsigned long long wp[4] = {pk2(wv.x), pk2(wv.y), pk2(wv.z), pk2(wv.w)};
        #pragma unroll
        for (int c = 0; c < 4; c++) {
            ffma2(acc[0][c], X0.x, wp[c]);
            ffma2(acc[1][c], X0.y, wp[c]);
        }
    }

    #pragma unroll
    for (int p = 0; p < 2; p++) {
        float r0c[4], r1c[4];
        #pragma unroll
        for (int c = 0; c < 4; c++) {
            float2 f = up2(acc[p][c]);
            r0c[c] = f.x + Bs[tc * 4 + c];
            r1c[c] = f.y + Bs[tc * 4 + c];
        }
        int rowa = r0 + tr * 4 + 2 * p;
        if (act == 2) {
            __half2* Yh = (__half2*)Y;
            uint2 o0, o1;
            o0.x = f2h2(r0c[1] * 0.5f, r0c[0] * 0.5f);
            o0.y = f2h2(r0c[3] * 0.5f, r0c[2] * 0.5f);
            o1.x = f2h2(r1c[1] * 0.5f, r1c[0] * 0.5f);
            o1.y = f2h2(r1c[3] * 0.5f, r1c[2] * 0.5f);
            *(uint2*)&Yh[(size_t)rowa * 32 + tc * 2]       = o0;
            *(uint2*)&Yh[(size_t)(rowa + 1) * 32 + tc * 2] = o1;
        } else {
            float4 o0 = make_float4(r0c[0], r0c[1], r0c[2], r0c[3]);
            float4 o1 = make_float4(r1c[0], r1c[1], r1c[2], r1c[3]);
            *(float4*)&Y[(size_t)rowa * 64 + tc * 4]       = o0;
            *(float4*)&Y[(size_t)(rowa + 1) * 64 + tc * 4] = o1;
        }
    }
}

// ============================================================================
// merged scan (+ zero g_ma): 128 blocks x 256 thr. (unchanged)
// ============================================================================
__global__ void __launch_bounds__(256) scan_k()
{
    __shared__ float parts[8][32];

    const int tid  = blockIdx.x * 256 + threadIdx.x;
    {
        float4 z4 = make_float4(0.f, 0.f, 0.f, 0.f);
        float4* mz = (float4*)g_ma;
        for (int i = tid; i < NROWS * 16; i += 32768) mz[i] = z4;
    }

    const int lane = threadIdx.x & 31;
    const int w    = threadIdx.x >> 5;
    const int col  = blockIdx.x * 32 + lane;
    const int t0   = w * 25;

    float s = 0.0f;
    #pragma unroll
    for (int t = 0; t < 25; t++)
        s += g_y3[(size_t)(t0 + t) * BH + col];
    parts[w][lane] = s;
    __syncthreads();

    float acc = 0.0f;
    #pragma unroll
    for (int p = 0; p < 7; p++) {
        float v = parts[p][lane];
        if (p < w) acc += v;
    }

    #pragma unroll
    for (int t = 0; t < 25; t++) {
        size_t o = (size_t)(t0 + t) * BH + col;
        acc += g_y3[o];
        float invt = __fdividef(1.0f, (float)(t0 + t + 1));
        g_qh[o] = __float2half((g_y2[o] + acc * invt) * 0.5f);
    }
}

// ============================================================================
// attention: grid (16, 64). (unchanged, 5 blocks/SM)
// ============================================================================
__global__ void __launch_bounds__(256, 5) attn_k(const float* __restrict__ inp,
                                                 const float* __restrict__ w0)
{
    __shared__ __align__(16) unsigned x1s[32 * 34];
    __shared__ __align__(16) unsigned qhs[32 * 34];
    __shared__ __align__(16) float2   insp[32][34];
    __shared__ __align__(16) unsigned w0h[32];
    __shared__ __align__(16) float    w0f[64];
    __shared__ __align__(16) float4   sst[8][32];

    const int b    = blockIdx.y;
    const int ibb  = c_IBB[blockIdx.x];
    const int jc   = c_JC[blockIdx.x];
    const int i0   = ibb * 32;
    const int tid  = threadIdx.x;
    const int wid  = tid >> 5;
    const int lane = tid & 31;
    const int iw   = wid << 2;

    if (tid < 64) w0f[tid] = w0[tid];
    if (tid >= 64 && tid < 96) {
        int t = tid - 64;
        w0h[t] = f2h2(w0[2 * t + 1], w0[2 * t]);
    }
    {
        int r = tid >> 3, c = tid & 7;
        int ii = i0 + r;
        uint4 v = make_uint4(0u, 0u, 0u, 0u);
        if (ii < T_DIM)
            v = *(const uint4*)&g_qh[(size_t)ii * BH + b * 64 + c * 8];
        unsigned* dst = &qhs[r * 34 + c * 4];
        *(uint2*)dst       = make_uint2(v.x, v.y);
        *(uint2*)(dst + 2) = make_uint2(v.z, v.w);
    }
    __syncthreads();

    float hw0 = 0.0f;
    #pragma unroll 16
    for (int h = 0; h < 64; h++) hw0 += w0f[h];
    hw0 *= 0.5f;

    float macc[4][2];
    #pragma unroll
    for (int k = 0; k < 4; k++) { macc[k][0] = 0.0f; macc[k][1] = 0.0f; }

    const int ntiles = (2 * jc + 1 <= ibb) ? 2 : 1;

    for (int t = 0; t < ntiles; t++) {
        const int j0 = (2 * jc + t) * 32;
        if (t) __syncthreads();
        {
            int jj = tid >> 3, c = tid & 7;
            int j = j0 + jj;
            uint4 v = make_uint4(0u, 0u, 0u, 0u);
            if (j < T_DIM)
                v = *(const uint4*)&g_x1h[((size_t)j * B_DIM + b) * 32 + c * 4];
            unsigned* dst = &x1s[jj * 34 + c * 4];
            *(uint2*)dst       = make_uint2(v.x, v.y);
            *(uint2*)(dst + 2) = make_uint2(v.z, v.w);
        }
        {
            int jj = tid >> 3;
            int h4 = (tid & 7) << 2;
            int j = j0 + jj;
            float4 z4 = make_float4(0.f, 0.f, 0.f, 0.f);
            float4 ia = z4, ib = z4;
            if (j < T_DIM) {
                const float* pi = &inp[(size_t)j * BH + b * 64];
                ia = *(const float4*)(pi + h4);
                ib = *(const float4*)(pi + h4 + 32);
            }
            *(float4*)&insp[jj][h4]     = make_float4(ia.x, ib.x, ia.y, ib.y);
            *(float4*)&insp[jj][h4 + 2] = make_float4(ia.z, ib.z, ia.w, ib.w);
        }
        __syncthreads();

        unsigned accA[4], accB[4];
        #pragma unroll
        for (int k = 0; k < 4; k++) { accA[k] = 0u; accB[k] = 0u; }

        const unsigned* xrow = &x1s[lane * 34];
        const unsigned* q0r  = &qhs[(iw + 0) * 34];
        const unsigned* q1r  = &qhs[(iw + 1) * 34];
        const unsigned* q2r  = &qhs[(iw + 2) * 34];
        const unsigned* q3r  = &qhs[(iw + 3) * 34];

        #pragma unroll
        for (int p = 0; p < 16; p++) {
            uint2 xv = *(const uint2*)&xrow[2 * p];
            uint2 wv = *(const uint2*)&w0h[2 * p];
            uint2 q0 = *(const uint2*)&q0r[2 * p];
            uint2 q1 = *(const uint2*)&q1r[2 * p];
            uint2 q2 = *(const uint2*)&q2r[2 * p];
            uint2 q3 = *(const uint2*)&q3r[2 * p];
            accA[0] = hfma2u(wv.x, tanh2u(hadd2u(xv.x, q0.x)), accA[0]);
            accA[1] = hfma2u(wv.x, tanh2u(hadd2u(xv.x, q1.x)), accA[1]);
            accA[2] = hfma2u(wv.x, tanh2u(hadd2u(xv.x, q2.x)), accA[2]);
            accA[3] = hfma2u(wv.x, tanh2u(hadd2u(xv.x, q3.x)), accA[3]);
            accB[0] = hfma2u(wv.y, tanh2u(hadd2u(xv.y, q0.y)), accB[0]);
            accB[1] = hfma2u(wv.y, tanh2u(hadd2u(xv.y, q1.y)), accB[1]);
            accB[2] = hfma2u(wv.y, tanh2u(hadd2u(xv.y, q2.y)), accB[2]);
            accB[3] = hfma2u(wv.y, tanh2u(hadd2u(xv.y, q3.y)), accB[3]);
        }

        const int j   = j0 + lane;
        const int ib2 = i0 + iw;
        float sv[4];
        #pragma unroll
        for (int k = 0; k < 4; k++) {
            float2 fa = h22f2(accA[k]);
            float2 fb = h22f2(accB[k]);
            float d = (fa.x + fa.y) + (fb.x + fb.y);
            sv[k] = (j <= ib2 + k && j < T_DIM) ? fmaf(0.5f, d, hw0) : 0.0f;
        }

        sst[wid][lane] = make_float4(sv[0], sv[1], sv[2], sv[3]);
        __syncwarp();

        #pragma unroll 8
        for (int jj = 0; jj < 32; jj++) {
            float4 s4 = sst[wid][jj];
            float2 vi = insp[jj][lane];
            macc[0][0] += s4.x * vi.x; macc[0][1] += s4.x * vi.y;
            macc[1][0] += s4.y * vi.x; macc[1][1] += s4.y * vi.y;
            macc[2][0] += s4.z * vi.x; macc[2][1] += s4.z * vi.y;
            macc[3][0] += s4.w * vi.x; macc[3][1] += s4.w * vi.y;
        }
        __syncwarp();
    }

    #pragma unroll
    for (int k = 0; k < 4; k++) {
        int i = i0 + iw + k;
        if (i < T_DIM) {
            size_t o = (size_t)i * BH + b * 64;
            atomicAdd(&g_ma[o + lane],      macc[k][0]);
            atomicAdd(&g_ma[o + lane + 32], macc[k][1]);
        }
    }
}

// ============================================================================
// tower_k (tf32 HMMA, permuted-k layout): grid (200, 4), 256 thr.
// q(k) = (k&3)*16 + (k>>2): a thread's fragment elements for two consecutive
// k-steps are one contiguous float4 -> LDS.128 fragment loads.
// ============================================================================
struct TowArgs {
    const float* W0[4]; const float* B0[4];
    const float* W1[4]; const float* B1[4];
};

__global__ void __launch_bounds__(256, 4) tower_k(TowArgs ta,
                                                  const float* __restrict__ inp)
{
    __shared__ __align__(16) float XT[64][68];    // X permuted [m][q(k)]
    __shared__ __align__(16) float WT0[64][68];   // W permuted [n][q(k)]; reused for W1
    __shared__ __align__(16) float H0[64][68];    // hidden permuted [m][q(c)]
    __shared__ float B0s[64], B1s[32];

    const int tw  = blockIdx.y;
    const int tid = threadIdx.x;
    const int r0  = blockIdx.x * 64;
    const float* __restrict__ Xsrc = (tw & 1) ? inp : (const float*)g_ma;

    const int wid  = tid >> 5;
    const int lane = tid & 31;
    const int gid  = lane >> 2;   // 0..7
    const int ctid = lane & 3;    // 0..3
    const int m    = (wid & 3) * 16;

    // X fill (permuted): row r, float4 over k=4j..4j+3 -> q = (k&3)*16 + j
    for (int idx = tid; idx < 1024; idx += 256) {
        int r = idx >> 4, j = idx & 15;
        float4 v = *(const float4*)&Xsrc[(size_t)(r0 + r) * 64 + 4 * j];
        XT[r][j]      = v.x;
        XT[r][16 + j] = v.y;
        XT[r][32 + j] = v.z;
        XT[r][48 + j] = v.w;
    }
    // W0 fill (transposed + permuted): W0 is [k][n]
    for (int idx = tid; idx < 1024; idx += 256) {
        int k  = idx & 63;
        int n4 = (idx >> 6) << 2;
        float4 v = *(const float4*)&ta.W0[tw][(size_t)k * 64 + n4];
        int q = ((k & 3) << 4) + (k >> 2);
        WT0[n4 + 0][q] = v.x; WT0[n4 + 1][q] = v.y;
        WT0[n4 + 2][q] = v.z; WT0[n4 + 3][q] = v.w;
    }
    if (tid < 64) B0s[tid] = ta.B0[tw][tid];
    if (tid < 32) B1s[tid] = ta.B1[tw][tid];
    __syncthreads();

    // ---- L0: D[64][64] = X @ W0, warp = m16 x n32, 2 k-steps per float4 ----
    {
        const int nh = (wid >> 2) * 32;
        const int qf = ctid * 16;     // fragment column base
        float d[4][4];
        #pragma unroll
        for (int nt = 0; nt < 4; nt++)
            #pragma unroll
            for (int c = 0; c < 4; c++) d[nt][c] = 0.0f;

        #pragma unroll
        for (int ksp = 0; ksp < 4; ksp++) {
            float4 A0 = *(const float4*)&XT[m + gid][qf + 4 * ksp];
            float4 A1 = *(const float4*)&XT[m + gid + 8][qf + 4 * ksp];
            #pragma unroll
            for (int nt = 0; nt < 4; nt++) {
                float4 Bv = *(const float4*)&WT0[nh + nt * 8 + gid][qf + 4 * ksp];
                mma_tf32(d[nt][0], d[nt][1], d[nt][2], d[nt][3],
                         FU(A0.x), FU(A1.x), FU(A0.y), FU(A1.y), FU(Bv.x), FU(Bv.y));
                mma_tf32(d[nt][0], d[nt][1], d[nt][2], d[nt][3],
                         FU(A0.z), FU(A1.z), FU(A0.w), FU(A1.w), FU(Bv.z), FU(Bv.w));
            }
        }
        #pragma unroll
        for (int nt = 0; nt < 4; nt++) {
            int c  = nh + nt * 8 + 2 * ctid;
            int qc = ((c & 3) << 4) + (c >> 2);     // q(c+1) = qc + 16
            H0[m + gid][qc]          = leakyf(d[nt][0] + B0s[c]);
            H0[m + gid][qc + 16]     = leakyf(d[nt][1] + B0s[c + 1]);
            H0[m + gid + 8][qc]      = leakyf(d[nt][2] + B0s[c]);
            H0[m + gid + 8][qc + 16] = leakyf(d[nt][3] + B0s[c + 1]);
        }
    }
    __syncthreads();   // L0 done: WT0 reads + H0 writes complete

    // W1 fill (transposed + permuted) into WT0's buffer: W1 is [k=64][n=32]
    for (int idx = tid; idx < 512; idx += 256) {
        int k  = idx & 63;
        int n4 = (idx >> 6) << 2;
        float4 v = *(const float4*)&ta.W1[tw][(size_t)k * 32 + n4];
        int q = ((k & 3) << 4) + (k >> 2);
        WT0[n4 + 0][q] = v.x; WT0[n4 + 1][q] = v.y;
        WT0[n4 + 2][q] = v.z; WT0[n4 + 3][q] = v.w;
    }
    __syncthreads();

    // ---- L1: E[64][32] = H0 @ W1, warp = m16 x n16 ----
    {
        const int nh1 = (wid >> 2) * 16;
        const int qf  = ctid * 16;
        float e[2][4];
        #pragma unroll
        for (int nt = 0; nt < 2; nt++)
            #pragma unroll
            for (int c = 0; c < 4; c++) e[nt][c] = 0.0f;

        #pragma unroll
        for (int ksp = 0; ksp < 4; ksp++) {
            float4 A0 = *(const float4*)&H0[m + gid][qf + 4 * ksp];
            float4 A1 = *(const float4*)&H0[m + gid + 8][qf + 4 * ksp];
            #pragma unroll
            for (int nt = 0; nt < 2; nt++) {
                float4 Bv = *(const float4*)&WT0[nh1 + nt * 8 + gid][qf + 4 * ksp];
                mma_tf32(e[nt][0], e[nt][1], e[nt][2], e[nt][3],
                         FU(A0.x), FU(A1.x), FU(A0.y), FU(A1.y), FU(Bv.x), FU(Bv.y));
                mma_tf32(e[nt][0], e[nt][1], e[nt][2], e[nt][3],
                         FU(A0.z), FU(A1.z), FU(A0.w), FU(A1.w), FU(Bv.z), FU(Bv.w));
            }
        }

        float* dst = g_t1 + (size_t)tw * NROWS * 32;
        #pragma unroll
        for (int nt = 0; nt < 2; nt++) {
            int c = nh1 + nt * 8 + 2 * ctid;
            float2 v0, v1;
            v0.x = leakyf(e[nt][0] + B1s[c]);
            v0.y = leakyf(e[nt][1] + B1s[c + 1]);
            v1.x = leakyf(e[nt][2] + B1s[c]);
            v1.y = leakyf(e[nt][3] + B1s[c + 1]);
            *(float2*)&dst[(size_t)(r0 + m + gid) * 32 + c]     = v0;
            *(float2*)&dst[(size_t)(r0 + m + gid + 8) * 32 + c] = v1;
        }
    }
}

// ============================================================================
// final: pc = sig(dot32(t1[0],t1[1])), pv = sig(dot32(t1[2],t1[3])) * pc
// ============================================================================
__global__ void __launch_bounds__(256) final_k(float* __restrict__ out)
{
    int r = blockIdx.x * 256 + threadIdx.x;   // 12800 threads
    const float4* pa = (const float4*)(g_t1 + (size_t)0 * NROWS * 32 + (size_t)r * 32);
    const float4* pb = (const float4*)(g_t1 + (size_t)1 * NROWS * 32 + (size_t)r * 32);
    const float4* va = (const float4*)(g_t1 + (size_t)2 * NROWS * 32 + (size_t)r * 32);
    const float4* vb = (const float4*)(g_t1 + (size_t)3 * NROWS * 32 + (size_t)r * 32);
    float zc = 0.0f, zv = 0.0f;
    #pragma unroll
    for (int k = 0; k < 8; k++) {
        float4 a = pa[k], b = pb[k];
        zc += a.x * b.x + a.y * b.y + a.z * b.z + a.w * b.w;
        float4 c = va[k], d = vb[k];
        zv += c.x * d.x + c.y * d.y + c.z * d.z + c.w * d.w;
    }
    float pc = sigf(zc);
    float pv = sigf(zv) * pc;
    out[r]         = pc;
    out[NROWS + r] = pv;
}

// ============================================================================
extern "C" void kernel_launch(void* const* d_in, const int* in_sizes, int n_in,
                              void* d_out, int out_size)
{
    (void)in_sizes; (void)n_in; (void)out_size;
    const float* inp     = (const float*)d_in[0];
    const float* w1k     = (const float*)d_in[1];
    const float* w1b     = (const float*)d_in[2];
    const float* w2k     = (const float*)d_in[3];
    const float* w3k     = (const float*)d_in[4];
    const float* w0k     = (const float*)d_in[5];
    const float* pc_a0_k = (const float*)d_in[6],  *pc_a0_b = (const float*)d_in[7];
    const float* pc_b0_k = (const float*)d_in[8],  *pc_b0_b = (const float*)d_in[9];
    const float* pc_a1_k = (const float*)d_in[10], *pc_a1_b = (const float*)d_in[11];
    const float* pc_b1_k = (const float*)d_in[12], *pc_b1_b = (const float*)d_in[13];
    const float* pv_a0_k = (const float*)d_in[14], *pv_a0_b = (const float*)d_in[15];
    const float* pv_b0_k = (const float*)d_in[16], *pv_b0_b = (const float*)d_in[17];
    const float* pv_a1_k = (const float*)d_in[18], *pv_a1_b = (const float*)d_in[19];
    const float* pv_b1_k = (const float*)d_in[20], *pv_b1_b = (const float*)d_in[21];

    float *x1h, *y2, *y3;
    cudaGetSymbolAddress((void**)&x1h, g_x1h);
    cudaGetSymbolAddress((void**)&y2, g_y2);
    cudaGetSymbolAddress((void**)&y3, g_y3);

    // 1) x1 (-> half2, *0.5), y2, y3
    GemmBatch A = {};
    A.X[0] = inp; A.W[0] = w1k; A.B[0] = w1b;     A.Y[0] = x1h; A.act[0] = 2;
    A.X[1] = inp; A.W[1] = w2k; A.B[1] = nullptr; A.Y[1] = y2;  A.act[1] = 0;
    A.X[2] = inp; A.W[2] = w3k; A.B[2] = nullptr; A.Y[2] = y3;  A.act[2] = 0;
    gemm64_k<<<dim3(NROWS / 64, 3), 256>>>(A);

    // 2) merged scan (also zeroes g_ma); emits q in half
    scan_k<<<BH / 32, 256>>>();

    // 3) scores + m_a
    attn_k<<<dim3(16, B_DIM), 256>>>(inp, w0k);

    // 4) towers via tf32 HMMA (permuted-k fragment layout)
    TowArgs ta = {};
    ta.W0[0] = pc_a0_k; ta.B0[0] = pc_a0_b; ta.W1[0] = pc_a1_k; ta.B1[0] = pc_a1_b;
    ta.W0[1] = pc_b0_k; ta.B0[1] = pc_b0_b; ta.W1[1] = pc_b1_k; ta.B1[1] = pc_b1_b;
    ta.W0[2] = pv_a0_k; ta.B0[2] = pv_a0_b; ta.W1[2] = pv_a1_k; ta.B1[2] = pv_a1_b;
    ta.W0[3] = pv_b0_k; ta.B0[3] = pv_b0_b; ta.W1[3] = pv_b1_k; ta.B1[3] = pv_b1_b;
    tower_k<<<dim3(NROWS / 64, 4), 256>>>(ta, inp);

    // 5) product-dot + sigmoid -> out
    final_k<<<NROWS / 256, 256>>>((float*)d_out);
}

// round 17
// speedup vs baseline: 1.1184x; 1.1184x over previous
#include <cuda_runtime.h>
#include <cuda_fp16.h>

#define T_DIM 200
#define B_DIM 64
#define E_DIM 64
#define NROWS (T_DIM * B_DIM)   // 12800
#define BH (B_DIM * E_DIM)      // 4096
#define LOG2E 1.4426950408889634f

// ---- scratch ----
__device__ __half2 g_x1h[NROWS * 32];   // x1 pre-scaled by 0.5, half2 packed
__device__ float   g_y2[NROWS * E_DIM];
__device__ float   g_y3[NROWS * E_DIM];
__device__ __half  g_qh[NROWS * E_DIM]; // q pre-scaled by 0.5, half
__device__ float   g_ma[NROWS * E_DIM];
__device__ float   g_t1[4 * NROWS * 32];  // tower L1 outputs

__constant__ int c_IBB[16] = {0,1,2,2,3,3,4,4,4,5,5,5,6,6,6,6};
__constant__ int c_JC [16] = {0,0,0,1,0,1,0,1,2,0,1,2,0,1,2,3};

__device__ __forceinline__ float ex2f(float x) {
    float r; asm("ex2.approx.f32 %0, %1;" : "=f"(r) : "f"(x)); return r;
}
__device__ __forceinline__ float rcpf(float x) {
    float r; asm("rcp.approx.f32 %0, %1;" : "=f"(r) : "f"(x)); return r;
}
__device__ __forceinline__ float sigf(float v) {
    return rcpf(1.0f + ex2f(-v * LOG2E));
}
__device__ __forceinline__ float leakyf(float v) {
    return (v >= 0.0f) ? v : 0.3f * v;
}
// ---- f16x2 helpers ----
__device__ __forceinline__ unsigned tanh2u(unsigned x) {
    unsigned r; asm("tanh.approx.f16x2 %0, %1;" : "=r"(r) : "r"(x)); return r;
}
__device__ __forceinline__ unsigned hadd2u(unsigned a, unsigned b) {
    unsigned r; asm("add.f16x2 %0, %1, %2;" : "=r"(r) : "r"(a), "r"(b)); return r;
}
__device__ __forceinline__ unsigned hfma2u(unsigned a, unsigned b, unsigned c) {
    unsigned r; asm("fma.rn.f16x2 %0, %1, %2, %3;" : "=r"(r) : "r"(a), "r"(b), "r"(c)); return r;
}
__device__ __forceinline__ unsigned f2h2(float hi, float lo) {
    unsigned r; asm("cvt.rn.f16x2.f32 %0, %1, %2;" : "=r"(r) : "f"(hi), "f"(lo)); return r;
}
__device__ __forceinline__ float2 h22f2(unsigned u) {
    float2 f;
    asm("{ .reg .f16 l, h; mov.b32 {l, h}, %2; cvt.f32.f16 %0, l; cvt.f32.f16 %1, h; }"
        : "=f"(f.x), "=f"(f.y) : "r"(u));
    return f;
}
// ---- tf32 mma (m16n8k8, row.col) ----
__device__ __forceinline__ void mma_tf32(float& d0, float& d1, float& d2, float& d3,
                                         unsigned a0, unsigned a1, unsigned a2, unsigned a3,
                                         unsigned b0, unsigned b1) {
    asm volatile(
        "mma.sync.aligned.m16n8k8.row.col.f32.tf32.tf32.f32 "
        "{%0,%1,%2,%3},{%4,%5,%6,%7},{%8,%9},{%0,%1,%2,%3};"
        : "+f"(d0), "+f"(d1), "+f"(d2), "+f"(d3)
        : "r"(a0), "r"(a1), "r"(a2), "r"(a3), "r"(b0), "r"(b1));
}

// ============================================================================
// GEMM (HOUT=64) via tf32 HMMA, up to 3 towers, 64-row tiles, grid (200, 3).
// act: 0=none, 1=leaky, 2 = *0.5 then half2 (Y is __half2*)
// Same MMA structure as tower_k L0 (proven R15).
// ============================================================================
struct GemmBatch {
    const float* X[3];
    const float* W[3];
    const float* B[3];
    float*       Y[3];
    int          act[3];
};

__global__ void __launch_bounds__(256) gemm64_k(GemmBatch gb)
{
    __shared__ __align__(16) float XT[64][68];   // X row-major [m][k]
    __shared__ __align__(16) float WT[64][68];   // W transposed [n][k]
    __shared__ float Bs[64];

    const int tw = blockIdx.y;
    const float* __restrict__ X  = gb.X[tw];
    const float* __restrict__ W  = gb.W[tw];
    const float* __restrict__ Bp = gb.B[tw];
    float* __restrict__ Y        = gb.Y[tw];
    const int act = gb.act[tw];

    const int tid = threadIdx.x;
    const int r0  = blockIdx.x * 64;

    const int wid  = tid >> 5;
    const int lane = tid & 31;
    const int gid  = lane >> 2;
    const int ctid = lane & 3;
    const int m    = (wid & 3) * 16;
    const int nh   = (wid >> 2) * 32;

    for (int idx = tid; idx < 64 * 16; idx += 256) {
        int r  = idx >> 4;
        int k4 = (idx & 15) << 2;
        *(float4*)&XT[r][k4] = *(const float4*)&X[(size_t)(r0 + r) * 64 + k4];
    }
    for (int idx = tid; idx < 1024; idx += 256) {
        int k  = idx & 63;
        int n4 = (idx >> 6) << 2;
        float4 v = *(const float4*)&W[(size_t)k * 64 + n4];
        WT[n4 + 0][k] = v.x; WT[n4 + 1][k] = v.y;
        WT[n4 + 2][k] = v.z; WT[n4 + 3][k] = v.w;
    }
    if (tid < 64) Bs[tid] = Bp ? Bp[tid] : 0.0f;
    __syncthreads();

    float d[4][4];
    #pragma unroll
    for (int nt = 0; nt < 4; nt++)
        #pragma unroll
        for (int c = 0; c < 4; c++) d[nt][c] = 0.0f;

    #pragma unroll
    for (int ks = 0; ks < 8; ks++) {
        const int kb = ks * 8;
        unsigned a0 = __float_as_uint(XT[m + gid][kb + ctid]);
        unsigned a1 = __float_as_uint(XT[m + gid + 8][kb + ctid]);
        unsigned a2 = __float_as_uint(XT[m + gid][kb + ctid + 4]);
        unsigned a3 = __float_as_uint(XT[m + gid + 8][kb + ctid + 4]);
        #pragma unroll
        for (int nt = 0; nt < 4; nt++) {
            const float* wr = &WT[nh + nt * 8 + gid][kb];
            unsigned b0 = __float_as_uint(wr[ctid]);
            unsigned b1 = __float_as_uint(wr[ctid + 4]);
            mma_tf32(d[nt][0], d[nt][1], d[nt][2], d[nt][3],
                     a0, a1, a2, a3, b0, b1);
        }
    }

    const int row0 = r0 + m + gid;
    #pragma unroll
    for (int nt = 0; nt < 4; nt++) {
        int c = nh + nt * 8 + 2 * ctid;
        float v00 = d[nt][0] + Bs[c];
        float v01 = d[nt][1] + Bs[c + 1];
        float v10 = d[nt][2] + Bs[c];
        float v11 = d[nt][3] + Bs[c + 1];
        if (act == 2) {
            __half2* Yh = (__half2*)Y;   // row stride 32 half2; c is even
            ((unsigned*)Yh)[(size_t)row0 * 32 + (c >> 1)]       = f2h2(v01 * 0.5f, v00 * 0.5f);
            ((unsigned*)Yh)[(size_t)(row0 + 8) * 32 + (c >> 1)] = f2h2(v11 * 0.5f, v10 * 0.5f);
        } else {
            if (act == 1) {
                v00 = leakyf(v00); v01 = leakyf(v01);
                v10 = leakyf(v10); v11 = leakyf(v11);
            }
            *(float2*)&Y[(size_t)row0 * 64 + c]       = make_float2(v00, v01);
            *(float2*)&Y[(size_t)(row0 + 8) * 64 + c] = make_float2(v10, v11);
        }
    }
}

// ============================================================================
// merged scan (+ zero g_ma): 128 blocks x 256 thr. (unchanged)
// ============================================================================
__global__ void __launch_bounds__(256) scan_k()
{
    __shared__ float parts[8][32];

    const int tid  = blockIdx.x * 256 + threadIdx.x;
    {
        float4 z4 = make_float4(0.f, 0.f, 0.f, 0.f);
        float4* mz = (float4*)g_ma;
        for (int i = tid; i < NROWS * 16; i += 32768) mz[i] = z4;
    }

    const int lane = threadIdx.x & 31;
    const int w    = threadIdx.x >> 5;
    const int col  = blockIdx.x * 32 + lane;
    const int t0   = w * 25;

    float s = 0.0f;
    #pragma unroll
    for (int t = 0; t < 25; t++)
        s += g_y3[(size_t)(t0 + t) * BH + col];
    parts[w][lane] = s;
    __syncthreads();

    float acc = 0.0f;
    #pragma unroll
    for (int p = 0; p < 7; p++) {
        float v = parts[p][lane];
        if (p < w) acc += v;
    }

    #pragma unroll
    for (int t = 0; t < 25; t++) {
        size_t o = (size_t)(t0 + t) * BH + col;
        acc += g_y3[o];
        float invt = __fdividef(1.0f, (float)(t0 + t + 1));
        g_qh[o] = __float2half((g_y2[o] + acc * invt) * 0.5f);
    }
}

// ============================================================================
// attention: grid (16, 64). (unchanged, 5 blocks/SM)
// ============================================================================
__global__ void __launch_bounds__(256, 5) attn_k(const float* __restrict__ inp,
                                                 const float* __restrict__ w0)
{
    __shared__ __align__(16) unsigned x1s[32 * 34];
    __shared__ __align__(16) unsigned qhs[32 * 34];
    __shared__ __align__(16) float2   insp[32][34];
    __shared__ __align__(16) unsigned w0h[32];
    __shared__ __align__(16) float    w0f[64];
    __shared__ __align__(16) float4   sst[8][32];

    const int b    = blockIdx.y;
    const int ibb  = c_IBB[blockIdx.x];
    const int jc   = c_JC[blockIdx.x];
    const int i0   = ibb * 32;
    const int tid  = threadIdx.x;
    const int wid  = tid >> 5;
    const int lane = tid & 31;
    const int iw   = wid << 2;

    if (tid < 64) w0f[tid] = w0[tid];
    if (tid >= 64 && tid < 96) {
        int t = tid - 64;
        w0h[t] = f2h2(w0[2 * t + 1], w0[2 * t]);
    }
    {
        int r = tid >> 3, c = tid & 7;
        int ii = i0 + r;
        uint4 v = make_uint4(0u, 0u, 0u, 0u);
        if (ii < T_DIM)
            v = *(const uint4*)&g_qh[(size_t)ii * BH + b * 64 + c * 8];
        unsigned* dst = &qhs[r * 34 + c * 4];
        *(uint2*)dst       = make_uint2(v.x, v.y);
        *(uint2*)(dst + 2) = make_uint2(v.z, v.w);
    }
    __syncthreads();

    float hw0 = 0.0f;
    #pragma unroll 16
    for (int h = 0; h < 64; h++) hw0 += w0f[h];
    hw0 *= 0.5f;

    float macc[4][2];
    #pragma unroll
    for (int k = 0; k < 4; k++) { macc[k][0] = 0.0f; macc[k][1] = 0.0f; }

    const int ntiles = (2 * jc + 1 <= ibb) ? 2 : 1;

    for (int t = 0; t < ntiles; t++) {
        const int j0 = (2 * jc + t) * 32;
        if (t) __syncthreads();
        {
            int jj = tid >> 3, c = tid & 7;
            int j = j0 + jj;
            uint4 v = make_uint4(0u, 0u, 0u, 0u);
            if (j < T_DIM)
                v = *(const uint4*)&g_x1h[((size_t)j * B_DIM + b) * 32 + c * 4];
            unsigned* dst = &x1s[jj * 34 + c * 4];
            *(uint2*)dst       = make_uint2(v.x, v.y);
            *(uint2*)(dst + 2) = make_uint2(v.z, v.w);
        }
        {
            int jj = tid >> 3;
            int h4 = (tid & 7) << 2;
            int j = j0 + jj;
            float4 z4 = make_float4(0.f, 0.f, 0.f, 0.f);
            float4 ia = z4, ib = z4;
            if (j < T_DIM) {
                const float* pi = &inp[(size_t)j * BH + b * 64];
                ia = *(const float4*)(pi + h4);
                ib = *(const float4*)(pi + h4 + 32);
            }
            *(float4*)&insp[jj][h4]     = make_float4(ia.x, ib.x, ia.y, ib.y);
            *(float4*)&insp[jj][h4 + 2] = make_float4(ia.z, ib.z, ia.w, ib.w);
        }
        __syncthreads();

        unsigned accA[4], accB[4];
        #pragma unroll
        for (int k = 0; k < 4; k++) { accA[k] = 0u; accB[k] = 0u; }

        const unsigned* xrow = &x1s[lane * 34];
        const unsigned* q0r  = &qhs[(iw + 0) * 34];
        const unsigned* q1r  = &qhs[(iw + 1) * 34];
        const unsigned* q2r  = &qhs[(iw + 2) * 34];
        const unsigned* q3r  = &qhs[(iw + 3) * 34];

        #pragma unroll
        for (int p = 0; p < 16; p++) {
            uint2 xv = *(const uint2*)&xrow[2 * p];
            uint2 wv = *(const uint2*)&w0h[2 * p];
            uint2 q0 = *(const uint2*)&q0r[2 * p];
            uint2 q1 = *(const uint2*)&q1r[2 * p];
            uint2 q2 = *(const uint2*)&q2r[2 * p];
            uint2 q3 = *(const uint2*)&q3r[2 * p];
            accA[0] = hfma2u(wv.x, tanh2u(hadd2u(xv.x, q0.x)), accA[0]);
            accA[1] = hfma2u(wv.x, tanh2u(hadd2u(xv.x, q1.x)), accA[1]);
            accA[2] = hfma2u(wv.x, tanh2u(hadd2u(xv.x, q2.x)), accA[2]);
            accA[3] = hfma2u(wv.x, tanh2u(hadd2u(xv.x, q3.x)), accA[3]);
            accB[0] = hfma2u(wv.y, tanh2u(hadd2u(xv.y, q0.y)), accB[0]);
            accB[1] = hfma2u(wv.y, tanh2u(hadd2u(xv.y, q1.y)), accB[1]);
            accB[2] = hfma2u(wv.y, tanh2u(hadd2u(xv.y, q2.y)), accB[2]);
            accB[3] = hfma2u(wv.y, tanh2u(hadd2u(xv.y, q3.y)), accB[3]);
        }

        const int j   = j0 + lane;
        const int ib2 = i0 + iw;
        float sv[4];
        #pragma unroll
        for (int k = 0; k < 4; k++) {
            float2 fa = h22f2(accA[k]);
            float2 fb = h22f2(accB[k]);
            float d = (fa.x + fa.y) + (fb.x + fb.y);
            sv[k] = (j <= ib2 + k && j < T_DIM) ? fmaf(0.5f, d, hw0) : 0.0f;
        }

        sst[wid][lane] = make_float4(sv[0], sv[1], sv[2], sv[3]);
        __syncwarp();

        #pragma unroll 8
        for (int jj = 0; jj < 32; jj++) {
            float4 s4 = sst[wid][jj];
            float2 vi = insp[jj][lane];
            macc[0][0] += s4.x * vi.x; macc[0][1] += s4.x * vi.y;
            macc[1][0] += s4.y * vi.x; macc[1][1] += s4.y * vi.y;
            macc[2][0] += s4.z * vi.x; macc[2][1] += s4.z * vi.y;
            macc[3][0] += s4.w * vi.x; macc[3][1] += s4.w * vi.y;
        }
        __syncwarp();
    }

    #pragma unroll
    for (int k = 0; k < 4; k++) {
        int i = i0 + iw + k;
        if (i < T_DIM) {
            size_t o = (size_t)i * BH + b * 64;
            atomicAdd(&g_ma[o + lane],      macc[k][0]);
            atomicAdd(&g_ma[o + lane + 32], macc[k][1]);
        }
    }
}

// ============================================================================
// tower_k (tf32 HMMA, R15 proven version): grid (200, 4), 256 thr.
// ============================================================================
struct TowArgs {
    const float* W0[4]; const float* B0[4];
    const float* W1[4]; const float* B1[4];
};

__global__ void __launch_bounds__(256, 4) tower_k(TowArgs ta,
                                                  const float* __restrict__ inp)
{
    __shared__ __align__(16) float XT[64][68];    // X row-major [m][k]
    __shared__ __align__(16) float WT0[64][68];   // W transposed [n][k]; reused for W1
    __shared__ __align__(16) float H0[64][68];    // hidden row-major [m][k]
    __shared__ float B0s[64], B1s[32];

    const int tw  = blockIdx.y;
    const int tid = threadIdx.x;
    const int r0  = blockIdx.x * 64;
    const float* __restrict__ Xsrc = (tw & 1) ? inp : (const float*)g_ma;

    const int wid  = tid >> 5;
    const int lane = tid & 31;
    const int gid  = lane >> 2;   // 0..7
    const int ctid = lane & 3;    // 0..3
    const int m    = (wid & 3) * 16;

    for (int idx = tid; idx < 64 * 16; idx += 256) {
        int r  = idx >> 4;
        int k4 = (idx & 15) << 2;
        *(float4*)&XT[r][k4] = *(const float4*)&Xsrc[(size_t)(r0 + r) * 64 + k4];
    }
    for (int idx = tid; idx < 1024; idx += 256) {
        int k  = idx & 63;
        int n4 = (idx >> 6) << 2;
        float4 v = *(const float4*)&ta.W0[tw][(size_t)k * 64 + n4];
        WT0[n4 + 0][k] = v.x; WT0[n4 + 1][k] = v.y;
        WT0[n4 + 2][k] = v.z; WT0[n4 + 3][k] = v.w;
    }
    if (tid < 64) B0s[tid] = ta.B0[tw][tid];
    if (tid < 32) B1s[tid] = ta.B1[tw][tid];
    __syncthreads();

    // ---- L0: D[64][64] = XT @ W0, warp = m16 x n32 ----
    {
        const int nh = (wid >> 2) * 32;
        float d[4][4];
        #pragma unroll
        for (int nt = 0; nt < 4; nt++)
            #pragma unroll
            for (int c = 0; c < 4; c++) d[nt][c] = 0.0f;

        #pragma unroll
        for (int ks = 0; ks < 8; ks++) {
            const int kb = ks * 8;
            unsigned a0 = __float_as_uint(XT[m + gid][kb + ctid]);
            unsigned a1 = __float_as_uint(XT[m + gid + 8][kb + ctid]);
            unsigned a2 = __float_as_uint(XT[m + gid][kb + ctid + 4]);
            unsigned a3 = __float_as_uint(XT[m + gid + 8][kb + ctid + 4]);
            #pragma unroll
            for (int nt = 0; nt < 4; nt++) {
                const float* wr = &WT0[nh + nt * 8 + gid][kb];
                unsigned b0 = __float_as_uint(wr[ctid]);
                unsigned b1 = __float_as_uint(wr[ctid + 4]);
                mma_tf32(d[nt][0], d[nt][1], d[nt][2], d[nt][3],
                         a0, a1, a2, a3, b0, b1);
            }
        }
        #pragma unroll
        for (int nt = 0; nt < 4; nt++) {
            int c = nh + nt * 8 + 2 * ctid;
            H0[m + gid][c]         = leakyf(d[nt][0] + B0s[c]);
            H0[m + gid][c + 1]     = leakyf(d[nt][1] + B0s[c + 1]);
            H0[m + gid + 8][c]     = leakyf(d[nt][2] + B0s[c]);
            H0[m + gid + 8][c + 1] = leakyf(d[nt][3] + B0s[c + 1]);
        }
    }
    __syncthreads();   // L0 done: WT0 reads + H0 writes complete

    // load W1 transposed into WT0's buffer ([32 n][64 k])
    for (int idx = tid; idx < 512; idx += 256) {
        int k  = idx & 63;
        int n4 = (idx >> 6) << 2;
        float4 v = *(const float4*)&ta.W1[tw][(size_t)k * 32 + n4];
        WT0[n4 + 0][k] = v.x; WT0[n4 + 1][k] = v.y;
        WT0[n4 + 2][k] = v.z; WT0[n4 + 3][k] = v.w;
    }
    __syncthreads();

    // ---- L1: E[64][32] = H0 @ W1, warp = m16 x n16 ----
    {
        const int nh1 = (wid >> 2) * 16;
        float e[2][4];
        #pragma unroll
        for (int nt = 0; nt < 2; nt++)
            #pragma unroll
            for (int c = 0; c < 4; c++) e[nt][c] = 0.0f;

        #pragma unroll
        for (int ks = 0; ks < 8; ks++) {
            const int kb = ks * 8;
            unsigned a0 = __float_as_uint(H0[m + gid][kb + ctid]);
            unsigned a1 = __float_as_uint(H0[m + gid + 8][kb + ctid]);
            unsigned a2 = __float_as_uint(H0[m + gid][kb + ctid + 4]);
            unsigned a3 = __float_as_uint(H0[m + gid + 8][kb + ctid + 4]);
            #pragma unroll
            for (int nt = 0; nt < 2; nt++) {
                const float* wr = &WT0[nh1 + nt * 8 + gid][kb];
                unsigned b0 = __float_as_uint(wr[ctid]);
                unsigned b1 = __float_as_uint(wr[ctid + 4]);
                mma_tf32(e[nt][0], e[nt][1], e[nt][2], e[nt][3],
                         a0, a1, a2, a3, b0, b1);
            }
        }

        float* dst = g_t1 + (size_t)tw * NROWS * 32;
        #pragma unroll
        for (int nt = 0; nt < 2; nt++) {
            int c = nh1 + nt * 8 + 2 * ctid;
            float2 v0, v1;
            v0.x = leakyf(e[nt][0] + B1s[c]);
            v0.y = leakyf(e[nt][1] + B1s[c + 1]);
            v1.x = leakyf(e[nt][2] + B1s[c]);
            v1.y = leakyf(e[nt][3] + B1s[c + 1]);
            *(float2*)&dst[(size_t)(r0 + m + gid) * 32 + c]     = v0;
            *(float2*)&dst[(size_t)(r0 + m + gid + 8) * 32 + c] = v1;
        }
    }
}

// ============================================================================
// final: pc = sig(dot32(t1[0],t1[1])), pv = sig(dot32(t1[2],t1[3])) * pc
// ============================================================================
__global__ void __launch_bounds__(256) final_k(float* __restrict__ out)
{
    int r = blockIdx.x * 256 + threadIdx.x;   // 12800 threads
    const float4* pa = (const float4*)(g_t1 + (size_t)0 * NROWS * 32 + (size_t)r * 32);
    const float4* pb = (const float4*)(g_t1 + (size_t)1 * NROWS * 32 + (size_t)r * 32);
    const float4* va = (const float4*)(g_t1 + (size_t)2 * NROWS * 32 + (size_t)r * 32);
    const float4* vb = (const float4*)(g_t1 + (size_t)3 * NROWS * 32 + (size_t)r * 32);
    float zc = 0.0f, zv = 0.0f;
    #pragma unroll
    for (int k = 0; k < 8; k++) {
        float4 a = pa[k], b = pb[k];
        zc += a.x * b.x + a.y * b.y + a.z * b.z + a.w * b.w;
        float4 c = va[k], d = vb[k];
        zv += c.x * d.x + c.y * d.y + c.z * d.z + c.w * d.w;
    }
    float pc = sigf(zc);
    float pv = sigf(zv) * pc;
    out[r]         = pc;
    out[NROWS + r] = pv;
}

// ============================================================================
extern "C" void kernel_launch(void* const* d_in, const int* in_sizes, int n_in,
                              void* d_out, int out_size)
{
    (void)in_sizes; (void)n_in; (void)out_size;
    const float* inp     = (const float*)d_in[0];
    const float* w1k     = (const float*)d_in[1];
    const float* w1b     = (const float*)d_in[2];
    const float* w2k     = (const float*)d_in[3];
    const float* w3k     = (const float*)d_in[4];
    const float* w0k     = (const float*)d_in[5];
    const float* pc_a0_k = (const float*)d_in[6],  *pc_a0_b = (const float*)d_in[7];
    const float* pc_b0_k = (const float*)d_in[8],  *pc_b0_b = (const float*)d_in[9];
    const float* pc_a1_k = (const float*)d_in[10], *pc_a1_b = (const float*)d_in[11];
    const float* pc_b1_k = (const float*)d_in[12], *pc_b1_b = (const float*)d_in[13];
    const float* pv_a0_k = (const float*)d_in[14], *pv_a0_b = (const float*)d_in[15];
    const float* pv_b0_k = (const float*)d_in[16], *pv_b0_b = (const float*)d_in[17];
    const float* pv_a1_k = (const float*)d_in[18], *pv_a1_b = (const float*)d_in[19];
    const float* pv_b1_k = (const float*)d_in[20], *pv_b1_b = (const float*)d_in[21];

    float *x1h, *y2, *y3;
    cudaGetSymbolAddress((void**)&x1h, g_x1h);
    cudaGetSymbolAddress((void**)&y2, g_y2);
    cudaGetSymbolAddress((void**)&y3, g_y3);

    // 1) x1 (-> half2, *0.5), y2, y3  (tf32 HMMA)
    GemmBatch A = {};
    A.X[0] = inp; A.W[0] = w1k; A.B[0] = w1b;     A.Y[0] = x1h; A.act[0] = 2;
    A.X[1] = inp; A.W[1] = w2k; A.B[1] = nullptr; A.Y[1] = y2;  A.act[1] = 0;
    A.X[2] = inp; A.W[2] = w3k; A.B[2] = nullptr; A.Y[2] = y3;  A.act[2] = 0;
    gemm64_k<<<dim3(NROWS / 64, 3), 256>>>(A);

    // 2) merged scan (also zeroes g_ma); emits q in half
    scan_k<<<BH / 32, 256>>>();

    // 3) scores + m_a
    attn_k<<<dim3(16, B_DIM), 256>>>(inp, w0k);

    // 4) towers via tf32 HMMA (R15 layout)
    TowArgs ta = {};
    ta.W0[0] = pc_a0_k; ta.B0[0] = pc_a0_b; ta.W1[0] = pc_a1_k; ta.B1[0] = pc_a1_b;
    ta.W0[1] = pc_b0_k; ta.B0[1] = pc_b0_b; ta.W1[1] = pc_b1_k; ta.B1[1] = pc_b1_b;
    ta.W0[2] = pv_a0_k; ta.B0[2] = pv_a0_b; ta.W1[2] = pv_a1_k; ta.B1[2] = pv_a1_b;
    ta.W0[3] = pv_b0_k; ta.B0[3] = pv_b0_b; ta.W1[3] = pv_b1_k; ta.B1[3] = pv_b1_b;
    tower_k<<<dim3(NROWS / 64, 4), 256>>>(ta, inp);

    // 5) product-dot + sigmoid -> out
    final_k<<<NROWS / 256, 256>>>((float*)d_out);
}